// round 12
// baseline (speedup 1.0000x reference)
#include <cuda_runtime.h>
#include <cuda_bf16.h>
#include <cstdint>

// MHC layer: B=8192, N=4, C=4096, f32. HBM-bound fusion.
// R12: combine R2 (2 CTAs/SM overlap) + R4 (prefetch pipeline) via
// HALF-ROW buffers: 3 x 32KB buffers/CTA = 96KB -> 2 CTAs/SM (192KB).
// 512 thr/CTA. Per row: halves h0,h1; next-h0 prefetch overlaps compute;
// next-h1 issues once passB(h0) frees its buffer. Pass B re-reads v from
// smem + recomputes agg (params stay in regs -> stores stay STG.128).

#define C_DIM 4096
#define NS 4
#define THREADS 512
#define NUM_CTAS 912            // 3 full waves of 304 (2/SM x 152)
#define EPS 1e-6f
#define HALF_F4 512                         // float4 per stream per half-row
#define HBUF_F4 (NS * HALF_F4)              // 2048 float4 = 32 KB
#define SMEM_BYTES (3 * HBUF_F4 * 16)       // 96 KB per CTA

__device__ __forceinline__ uint32_t smem_u32(const void* p) {
    uint32_t a;
    asm("{ .reg .u64 t; cvta.to.shared.u64 t, %1; cvt.u32.u64 %0, t; }"
        : "=r"(a) : "l"(p));
    return a;
}

// Load one half-row (4 streams x 512 float4) into buffer k. Each thread
// copies exactly the 4 float4 it will later read back (own-data visibility:
// no barrier needed after wait_group for pass A/B reads).
__device__ __forceinline__ void load_half(uint32_t sbuf, const float4* x4row,
                                          int h, int t) {
#pragma unroll
    for (int n = 0; n < NS; n++) {
        const float4* src = x4row + n * (C_DIM / 4) + h * HALF_F4 + t;
        asm volatile("cp.async.cg.shared.global [%0], [%1], 16;"
                     :: "r"(sbuf + (n * HALF_F4 + t) * 16), "l"(src));
    }
    asm volatile("cp.async.commit_group;");
}

__global__ __launch_bounds__(THREADS, 2)
void mhc_kernel(const float* __restrict__ x,
                const float* __restrict__ w,
                const float* __restrict__ H_pre,
                const float* __restrict__ H_post,
                const float* __restrict__ H_res,
                float* __restrict__ out,
                int B)
{
    extern __shared__ float4 sm[];          // [3][HBUF_F4]
    __shared__ float4 red4[THREADS / 32 / 4];   // 16 partials = 4 float4
    __shared__ float sp[24];                // hpre[4], hpost[4], P[16]

    const int t = threadIdx.x;

    // ---- balanced contiguous slab ----
    const int nb   = gridDim.x;
    const int base = B / nb;
    const int rem  = B - base * nb;
    const int bid  = blockIdx.x;
    const int b0   = bid * base + (bid < rem ? bid : rem);
    const int nrows = base + (bid < rem ? 1 : 0);

    const uint32_t sbase = smem_u32(sm);

    // ---- prologue: load row b0 halves h0->buf0, h1->buf1 ----
    {
        const float4* x4row = reinterpret_cast<const float4*>(x) + (size_t)b0 * (NS * C_DIM / 4);
        load_half(sbase + 0 * HBUF_F4 * 16, x4row, 0, t);
        load_half(sbase + 1 * HBUF_F4 * 16, x4row, 1, t);
    }

    // ---- thread 0: tiny parameter math while copies fly ----
    if (t == 0) {
#pragma unroll
        for (int n = 0; n < NS; n++) {
            sp[n]     = 1.0f / (1.0f + expf(-H_pre[n]));
            sp[4 + n] = 2.0f / (1.0f + expf(-H_post[n]));
        }
        float P[NS][NS];
#pragma unroll
        for (int i = 0; i < NS; i++)
#pragma unroll
            for (int j = 0; j < NS; j++)
                P[i][j] = expf(H_res[i * NS + j]);
#pragma unroll
        for (int it = 0; it < 3; it++) {
#pragma unroll
            for (int i = 0; i < NS; i++) {
                float inv = 1.0f / (P[i][0] + P[i][1] + P[i][2] + P[i][3] + EPS);
#pragma unroll
                for (int j = 0; j < NS; j++) P[i][j] *= inv;
            }
#pragma unroll
            for (int j = 0; j < NS; j++) {
                float inv = 1.0f / (P[0][j] + P[1][j] + P[2][j] + P[3][j] + EPS);
#pragma unroll
                for (int i = 0; i < NS; i++) P[i][j] *= inv;
            }
        }
#pragma unroll
        for (int i = 0; i < NS; i++)
#pragma unroll
            for (int j = 0; j < NS; j++)
                sp[8 + i * NS + j] = P[i][j];
    }
    __syncthreads();

    const float hp0 = sp[0], hp1 = sp[1], hp2 = sp[2], hp3 = sp[3];
    float Pr[NS][NS], hq[NS];
#pragma unroll
    for (int i = 0; i < NS; i++) {
        hq[i] = sp[4 + i];
#pragma unroll
        for (int j = 0; j < NS; j++) Pr[i][j] = sp[8 + i * NS + j];
    }

    const float4* __restrict__ wr = reinterpret_cast<const float4*>(w);

#pragma unroll 1
    for (int r = 0; r < nrows; r++) {
        const int b = b0 + r;
        const bool has_next = (r + 1 < nrows);
        const int k0 = (2 * r) % 3;         // buffer of h0
        const int k1 = (2 * r + 1) % 3;     // buffer of h1
        const int kn = (2 * r + 2) % 3;     // free: last used by row r-1 h1

        const float4* xn4 = reinterpret_cast<const float4*>(x) +
                            (size_t)(b + 1) * (NS * C_DIM / 4);

        // ---- prefetch next row h0 into the free buffer ----
        if (has_next)
            load_half(sbase + kn * HBUF_F4 * 16, xn4, 0, t);

        // ---- wait current row's two halves (leave next-h0 in flight) ----
        if (has_next)
            asm volatile("cp.async.wait_group 1;" ::: "memory");
        else
            asm volatile("cp.async.wait_group 0;" ::: "memory");

        // ---- pass A over both halves: gated agg + bf16 rt -> ss ----
        float ss = 0.0f;
#pragma unroll
        for (int h = 0; h < 2; h++) {
            const float4* bf = sm + (h == 0 ? k0 : k1) * HBUF_F4;
            const float4 v0 = bf[0 * HALF_F4 + t];
            const float4 v1 = bf[1 * HALF_F4 + t];
            const float4 v2 = bf[2 * HALF_F4 + t];
            const float4 v3 = bf[3 * HALF_F4 + t];
            float ax = hp0*v0.x + hp1*v1.x + hp2*v2.x + hp3*v3.x;
            float ay = hp0*v0.y + hp1*v1.y + hp2*v2.y + hp3*v3.y;
            float az = hp0*v0.z + hp1*v1.z + hp2*v2.z + hp3*v3.z;
            float aw = hp0*v0.w + hp1*v1.w + hp2*v2.w + hp3*v3.w;
            ax = __bfloat162float(__float2bfloat16(ax));
            ay = __bfloat162float(__float2bfloat16(ay));
            az = __bfloat162float(__float2bfloat16(az));
            aw = __bfloat162float(__float2bfloat16(aw));
            ss += ax*ax + ay*ay + az*az + aw*aw;
        }

        // ---- reduce: warp partials -> 1 barrier -> all threads sum 16 ----
#pragma unroll
        for (int off = 16; off > 0; off >>= 1)
            ss += __shfl_xor_sync(0xFFFFFFFFu, ss, off);
        if ((t & 31) == 0)
            reinterpret_cast<float*>(red4)[t >> 5] = ss;
        __syncthreads();
        float4 acc = red4[0];
#pragma unroll
        for (int q = 1; q < 4; q++) {
            const float4 p = red4[q];
            acc.x += p.x; acc.y += p.y; acc.z += p.z; acc.w += p.w;
        }
        const float inv_rms =
            rsqrtf(((acc.x + acc.y) + (acc.z + acc.w)) * (1.0f / C_DIM) + EPS);

        float4* __restrict__ out4 =
            reinterpret_cast<float4*>(out + (size_t)b * NS * C_DIM);

        // ---- pass B, half 0: re-read v, recompute agg, mix, store ----
        {
            const float4* bf = sm + k0 * HBUF_F4;
            const float4 v0 = bf[0 * HALF_F4 + t];
            const float4 v1 = bf[1 * HALF_F4 + t];
            const float4 v2 = bf[2 * HALF_F4 + t];
            const float4 v3 = bf[3 * HALF_F4 + t];
            float ax = hp0*v0.x + hp1*v1.x + hp2*v2.x + hp3*v3.x;
            float ay = hp0*v0.y + hp1*v1.y + hp2*v2.y + hp3*v3.y;
            float az = hp0*v0.z + hp1*v1.z + hp2*v2.z + hp3*v3.z;
            float aw = hp0*v0.w + hp1*v1.w + hp2*v2.w + hp3*v3.w;
            ax = __bfloat162float(__float2bfloat16(ax));
            ay = __bfloat162float(__float2bfloat16(ay));
            az = __bfloat162float(__float2bfloat16(az));
            aw = __bfloat162float(__float2bfloat16(aw));
            const float4 w4 = wr[0 * HALF_F4 + t];
            const float yx = ax * inv_rms * w4.x;
            const float yy = ay * inv_rms * w4.y;
            const float yz = az * inv_rms * w4.z;
            const float yw = aw * inv_rms * w4.w;
#pragma unroll
            for (int i = 0; i < NS; i++) {
                float4 o;
                o.x = Pr[i][0]*v0.x + Pr[i][1]*v1.x + Pr[i][2]*v2.x + Pr[i][3]*v3.x + hq[i]*yx;
                o.y = Pr[i][0]*v0.y + Pr[i][1]*v1.y + Pr[i][2]*v2.y + Pr[i][3]*v3.y + hq[i]*yy;
                o.z = Pr[i][0]*v0.z + Pr[i][1]*v1.z + Pr[i][2]*v2.z + Pr[i][3]*v3.z + hq[i]*yz;
                o.w = Pr[i][0]*v0.w + Pr[i][1]*v1.w + Pr[i][2]*v2.w + Pr[i][3]*v3.w + hq[i]*yw;
                out4[i * (C_DIM / 4) + 0 * HALF_F4 + t] = o;
            }
        }

        // h0 buffer fully read -> free it, then prefetch next row h1 into it
        __syncthreads();
        if (has_next)
            load_half(sbase + k0 * HBUF_F4 * 16, xn4, 1, t);

        // ---- pass B, half 1 ----
        {
            const float4* bf = sm + k1 * HBUF_F4;
            const float4 v0 = bf[0 * HALF_F4 + t];
            const float4 v1 = bf[1 * HALF_F4 + t];
            const float4 v2 = bf[2 * HALF_F4 + t];
            const float4 v3 = bf[3 * HALF_F4 + t];
            float ax = hp0*v0.x + hp1*v1.x + hp2*v2.x + hp3*v3.x;
            float ay = hp0*v0.y + hp1*v1.y + hp2*v2.y + hp3*v3.y;
            float az = hp0*v0.z + hp1*v1.z + hp2*v2.z + hp3*v3.z;
            float aw = hp0*v0.w + hp1*v1.w + hp2*v2.w + hp3*v3.w;
            ax = __bfloat162float(__float2bfloat16(ax));
            ay = __bfloat162float(__float2bfloat16(ay));
            az = __bfloat162float(__float2bfloat16(az));
            aw = __bfloat162float(__float2bfloat16(aw));
            const float4 w4 = wr[1 * HALF_F4 + t];
            const float yx = ax * inv_rms * w4.x;
            const float yy = ay * inv_rms * w4.y;
            const float yz = az * inv_rms * w4.z;
            const float yw = aw * inv_rms * w4.w;
#pragma unroll
            for (int i = 0; i < NS; i++) {
                float4 o;
                o.x = Pr[i][0]*v0.x + Pr[i][1]*v1.x + Pr[i][2]*v2.x + Pr[i][3]*v3.x + hq[i]*yx;
                o.y = Pr[i][0]*v0.y + Pr[i][1]*v1.y + Pr[i][2]*v2.y + Pr[i][3]*v3.y + hq[i]*yy;
                o.z = Pr[i][0]*v0.z + Pr[i][1]*v1.z + Pr[i][2]*v2.z + Pr[i][3]*v3.z + hq[i]*yz;
                o.w = Pr[i][0]*v0.w + Pr[i][1]*v1.w + Pr[i][2]*v2.w + Pr[i][3]*v3.w + hq[i]*yw;
                out4[i * (C_DIM / 4) + 1 * HALF_F4 + t] = o;
            }
        }

        // h1 buffer fully read before iter r+1 prefetches into it (kn' = k1)
        __syncthreads();
    }
}

extern "C" void kernel_launch(void* const* d_in, const int* in_sizes, int n_in,
                              void* d_out, int out_size)
{
    const float* x      = (const float*)d_in[0];  // [8192, 4, 4096]
    const float* w      = (const float*)d_in[1];  // [4096]
    const float* H_pre  = (const float*)d_in[2];  // [4]
    const float* H_post = (const float*)d_in[3];  // [4]
    const float* H_res  = (const float*)d_in[4];  // [4, 4]
    float* out = (float*)d_out;                   // [8192, 4, 4096]

    cudaFuncSetAttribute(mhc_kernel,
                         cudaFuncAttributeMaxDynamicSharedMemorySize, SMEM_BYTES);

    const int B = in_sizes[0] / (NS * C_DIM);     // 8192
    mhc_kernel<<<NUM_CTAS, THREADS, SMEM_BYTES>>>(x, w, H_pre, H_post, H_res, out, B);
}

// round 13
// speedup vs baseline: 1.0278x; 1.0278x over previous
#include <cuda_runtime.h>
#include <cuda_bf16.h>
#include <cstdint>

// MHC layer: B=8192, N=4, C=4096, f32. HBM-bound fusion.
// R13 = R11 chassis (double-buffered cp.async, 1024 thr, float4 STG,
// balanced slabs) with SMALL slabs: grid = 2128 = 14 x 152 SMs
// (14 full waves, slabs of 3-4 rows). More CTA handoffs per SM ->
// incoming CTA's prologue loads overlap outgoing CTA's final stores
// (trend: rows/CTA 8->78.7%, 9->78.0%, 54->75.7% DRAM).

#define C_DIM 4096
#define NS 4
#define THREADS 1024            // = C_DIM/4 -> one float4 per stream per thread
#define NUM_CTAS 2128           // 14 * 152
#define EPS 1e-6f
#define ROW_F4 (NS * C_DIM / 4)             // 4096 float4 per row buffer
#define SMEM_BYTES (2 * ROW_F4 * 16)        // 128 KB: two row buffers

__device__ __forceinline__ uint32_t smem_u32(const void* p) {
    uint32_t a;
    asm("{ .reg .u64 t; cvta.to.shared.u64 t, %1; cvt.u32.u64 %0, t; }"
        : "=r"(a) : "l"(p));
    return a;
}

__global__ __launch_bounds__(THREADS, 1)
void mhc_kernel(const float* __restrict__ x,
                const float* __restrict__ w,
                const float* __restrict__ H_pre,
                const float* __restrict__ H_post,
                const float* __restrict__ H_res,
                float* __restrict__ out,
                int B)
{
    extern __shared__ float4 sx[];          // [2][ROW_F4]
    __shared__ float red[THREADS / 32];
    __shared__ float sp[24];                // [0:4)=hpre [4:8)=hpost [8:24)=P

    const int t = threadIdx.x;

    // ---- balanced contiguous slab: base rows + first `rem` CTAs get +1 ----
    const int nb   = gridDim.x;
    const int base = B / nb;                          // 3
    const int rem  = B - base * nb;                   // 1808
    const int bid  = blockIdx.x;
    const int b0   = bid * base + (bid < rem ? bid : rem);
    const int nrows = base + (bid < rem ? 1 : 0);     // 3 or 4

    const uint32_t sbase = smem_u32(sx);

    // ---- prologue: prefetch first row into buffer 0 ----
    {
        const float4* __restrict__ xr =
            reinterpret_cast<const float4*>(x + (size_t)b0 * NS * C_DIM);
#pragma unroll
        for (int n = 0; n < NS; n++) {
            const int idx = n * THREADS + t;
            asm volatile("cp.async.cg.shared.global [%0], [%1], 16;"
                         :: "r"(sbase + idx * 16), "l"(xr + idx));
        }
        asm volatile("cp.async.commit_group;");
    }

    // ---- thread 0: tiny parameter math into smem while copies fly ----
    if (t == 0) {
#pragma unroll
        for (int n = 0; n < NS; n++) {
            sp[n]     = 1.0f / (1.0f + expf(-H_pre[n]));
            sp[4 + n] = 2.0f / (1.0f + expf(-H_post[n]));
        }
        float P[NS][NS];
#pragma unroll
        for (int i = 0; i < NS; i++)
#pragma unroll
            for (int j = 0; j < NS; j++)
                P[i][j] = expf(H_res[i * NS + j]);
#pragma unroll
        for (int it = 0; it < 3; it++) {
#pragma unroll
            for (int i = 0; i < NS; i++) {
                float inv = 1.0f / (P[i][0] + P[i][1] + P[i][2] + P[i][3] + EPS);
#pragma unroll
                for (int j = 0; j < NS; j++) P[i][j] *= inv;
            }
#pragma unroll
            for (int j = 0; j < NS; j++) {
                float inv = 1.0f / (P[0][j] + P[1][j] + P[2][j] + P[3][j] + EPS);
#pragma unroll
                for (int i = 0; i < NS; i++) P[i][j] *= inv;
            }
        }
#pragma unroll
        for (int i = 0; i < NS; i++)
#pragma unroll
            for (int j = 0; j < NS; j++)
                sp[8 + i * NS + j] = P[i][j];
    }
    __syncthreads();

    // ---- params into registers (kept across the row loop) ----
    const float hp0 = sp[0], hp1 = sp[1], hp2 = sp[2], hp3 = sp[3];
    float Pr[NS][NS], hq[NS];
#pragma unroll
    for (int i = 0; i < NS; i++) {
        hq[i] = sp[4 + i];
#pragma unroll
        for (int j = 0; j < NS; j++) Pr[i][j] = sp[8 + i * NS + j];
    }

    const float4* __restrict__ wr = reinterpret_cast<const float4*>(w);
    const float4 w4 = wr[t];                // loop-invariant weight chunk

    int parity = 0;
#pragma unroll 1
    for (int r = 0; r < nrows; r++) {
        const int b = b0 + r;
        const bool has_next = (r + 1 < nrows);

        // ---- prefetch next row into the other buffer ----
        if (has_next) {
            const float4* __restrict__ xr =
                reinterpret_cast<const float4*>(x + (size_t)(b + 1) * NS * C_DIM);
            const uint32_t sb = sbase + (1 - parity) * (ROW_F4 * 16);
#pragma unroll
            for (int n = 0; n < NS; n++) {
                const int idx = n * THREADS + t;
                asm volatile("cp.async.cg.shared.global [%0], [%1], 16;"
                             :: "r"(sb + idx * 16), "l"(xr + idx));
            }
            asm volatile("cp.async.commit_group;");
            asm volatile("cp.async.wait_group 1;" ::: "memory");
        } else {
            asm volatile("cp.async.wait_group 0;" ::: "memory");
        }
        __syncthreads();

        const float4* __restrict__ sb = sx + parity * ROW_F4;

        // ---- pass A: gated agg + bf16 round-trip -> sum of squares ----
        const float4 v0 = sb[0 * THREADS + t];
        const float4 v1 = sb[1 * THREADS + t];
        const float4 v2 = sb[2 * THREADS + t];
        const float4 v3 = sb[3 * THREADS + t];
        float ax = hp0*v0.x + hp1*v1.x + hp2*v2.x + hp3*v3.x;
        float ay = hp0*v0.y + hp1*v1.y + hp2*v2.y + hp3*v3.y;
        float az = hp0*v0.z + hp1*v1.z + hp2*v2.z + hp3*v3.z;
        float aw = hp0*v0.w + hp1*v1.w + hp2*v2.w + hp3*v3.w;
        ax = __bfloat162float(__float2bfloat16(ax));
        ay = __bfloat162float(__float2bfloat16(ay));
        az = __bfloat162float(__float2bfloat16(az));
        aw = __bfloat162float(__float2bfloat16(aw));
        float ss = ax*ax + ay*ay + az*az + aw*aw;

        // ---- block reduce (32 warps) ----
#pragma unroll
        for (int off = 16; off > 0; off >>= 1)
            ss += __shfl_xor_sync(0xFFFFFFFFu, ss, off);
        if ((t & 31) == 0) red[t >> 5] = ss;
        __syncthreads();
        if (t < 32) {
            float s = red[t];
#pragma unroll
            for (int off = 16; off > 0; off >>= 1)
                s += __shfl_xor_sync(0xFFFFFFFFu, s, off);
            if (t == 0) red[0] = s;
        }
        __syncthreads();
        const float inv_rms = rsqrtf(red[0] * (1.0f / C_DIM) + EPS);

        // ---- pass B: y_norm, 4x4 mix + gated add, float4 stores ----
        const float yx = ax * inv_rms * w4.x;
        const float yy = ay * inv_rms * w4.y;
        const float yz = az * inv_rms * w4.z;
        const float yw = aw * inv_rms * w4.w;

        float4* __restrict__ outr =
            reinterpret_cast<float4*>(out + (size_t)b * NS * C_DIM);
#pragma unroll
        for (int i = 0; i < NS; i++) {
            float4 o;
            o.x = Pr[i][0]*v0.x + Pr[i][1]*v1.x + Pr[i][2]*v2.x + Pr[i][3]*v3.x + hq[i]*yx;
            o.y = Pr[i][0]*v0.y + Pr[i][1]*v1.y + Pr[i][2]*v2.y + Pr[i][3]*v3.y + hq[i]*yy;
            o.z = Pr[i][0]*v0.z + Pr[i][1]*v1.z + Pr[i][2]*v2.z + Pr[i][3]*v3.z + hq[i]*yz;
            o.w = Pr[i][0]*v0.w + Pr[i][1]*v1.w + Pr[i][2]*v2.w + Pr[i][3]*v3.w + hq[i]*yw;
            outr[i * THREADS + t] = o;
        }

        // buffer fully read before next iter prefetches into it
        __syncthreads();
        parity ^= 1;
    }
}

extern "C" void kernel_launch(void* const* d_in, const int* in_sizes, int n_in,
                              void* d_out, int out_size)
{
    const float* x      = (const float*)d_in[0];  // [8192, 4, 4096]
    const float* w      = (const float*)d_in[1];  // [4096]
    const float* H_pre  = (const float*)d_in[2];  // [4]
    const float* H_post = (const float*)d_in[3];  // [4]
    const float* H_res  = (const float*)d_in[4];  // [4, 4]
    float* out = (float*)d_out;                   // [8192, 4, 4096]

    cudaFuncSetAttribute(mhc_kernel,
                         cudaFuncAttributeMaxDynamicSharedMemorySize, SMEM_BYTES);

    const int B = in_sizes[0] / (NS * C_DIM);     // 8192
    mhc_kernel<<<NUM_CTAS, THREADS, SMEM_BYTES>>>(x, w, H_pre, H_post, H_res, out, B);
}